// round 15
// baseline (speedup 1.0000x reference)
#include <cuda_runtime.h>
#include <cuda_fp16.h>
#include <cstdint>

#define EPS 1e-5f

// Problem dims
constexpr int T_   = 4;
constexpr int B_   = 16;
constexpr int C_   = 256;
constexpr int MED  = 512;
constexpr int HW   = 1024;   // 32*32
constexpr int IMGS = 64;     // T*B

constexpr size_t N_X  = (size_t)T_ * B_ * C_  * HW;
constexpr size_t N_Y1 = (size_t)T_ * B_ * MED * HW;
constexpr size_t STRIDE_T_C = (size_t)B_ * C_  * HW;
constexpr size_t STRIDE_T_M = (size_t)B_ * MED * HW;

constexpr float LO_SCALE   = 2048.0f;          // 2^11
constexpr float LO_INV     = 1.0f / 2048.0f;

// padded spatial tile for branch-free 3x3 conv (R12 layout)
#define PH 34
#define PW 36
#define PTILE (PH * PW)   // 1224

// ---------------- scratch (device globals) ---------------------------------
__device__ unsigned char g_s1[N_X];     // stage1 spikes  [T,B,C,HW]
__device__ unsigned char g_s2[N_Y1];    // stage2 spikes  [T,B,MED,HW] (fused LIF2)
__device__ unsigned char g_s3[N_Y1];    // stage3 spikes  [T,B,MED,HW]
__device__ __half        g_zv[N_X];     // stage3 1x1 conv variable part (fp16)

__device__ __half g_W1hi[MED * C_];
__device__ __half g_W1lo[MED * C_];     // (w-hi)*2^11
__device__ __half g_W2hi[C_ * MED];     // single-pass fp16 (no threshold downstream)
__device__ float g_bias1[MED];          // b1 - m1*inv1
__device__ float g_wdw2f[MED * 9];      // w_dw2 * inv2(c)
__device__ float g_c2[MED];             // b2 - m2*inv2
__device__ float g_wr2f[C_ * 9];        // w_rep2 * inv3(o)
__device__ float g_Bt[C_];              // total bias for final dw+BN3

// ---------------- merged prep kernel ---------------------------------------
__device__ __forceinline__ void split2h(float w, __half& hi, __half& lo)
{
    hi = __float2half_rn(w);
    float r = w - __half2float(hi);
    lo = __float2half_rn(r * LO_SCALE);
}

__global__ void prep_all(const float* __restrict__ w_pw1,
                         const float* __restrict__ g1, const float* __restrict__ b1,
                         const float* __restrict__ m1, const float* __restrict__ v1,
                         const float* __restrict__ w_dw2,
                         const float* __restrict__ g2, const float* __restrict__ b2,
                         const float* __restrict__ m2, const float* __restrict__ v2,
                         const float* __restrict__ gp, const float* __restrict__ bp,
                         const float* __restrict__ mp, const float* __restrict__ vp,
                         const float* __restrict__ w_rep1, const float* __restrict__ w_rep2,
                         const float* __restrict__ g3, const float* __restrict__ b3,
                         const float* __restrict__ m3, const float* __restrict__ v3)
{
    int bx = blockIdx.x;
    int tid = threadIdx.x;   // 256

    if (bx < 512) {
        int o = bx, k = tid;
        float inv1 = g1[o] / sqrtf(v1[o] + EPS);
        float w = w_pw1[o * C_ + k] * inv1;
        __half hi, lo;
        split2h(w, hi, lo);
        g_W1hi[o * C_ + k] = hi;
        g_W1lo[o * C_ + k] = lo;
    } else if (bx < 768) {
        int o = bx - 512;
#pragma unroll
        for (int kk = 0; kk < 2; kk++) {
            int k = tid + kk * 256;
            float invp = gp[k] / sqrtf(vp[k] + EPS);
            float w = w_rep1[o * MED + k] * invp;
            g_W2hi[o * MED + k] = __float2half_rn(w);
        }
    } else if (bx < 1024) {
        int o = bx - 768;
        float p = 0.f;
#pragma unroll
        for (int kk = 0; kk < 2; kk++) {
            int k = tid + kk * 256;
            float invp = gp[k] / sqrtf(vp[k] + EPS);
            float cpk = bp[k] - mp[k] * invp;
            p += w_rep1[o * MED + k] * cpk;
        }
        __shared__ float red[256];
        red[tid] = p;
        __syncthreads();
        for (int s = 128; s > 0; s >>= 1) {
            if (tid < s) red[tid] += red[tid + s];
            __syncthreads();
        }
        if (tid == 0) {
            float cb = red[0];
            float inv3 = g3[o] / sqrtf(v3[o] + EPS);
            float sw = 0.f;
#pragma unroll
            for (int j = 0; j < 9; j++) {
                float wv = w_rep2[o * 9 + j];
                g_wr2f[o * 9 + j] = wv * inv3;
                sw += wv;
            }
            g_Bt[o] = (b3[o] - m3[o] * inv3) + inv3 * cb * sw;
        }
    } else {
#pragma unroll
        for (int kk = 0; kk < 2; kk++) {
            int i = tid + kk * 256;
            float inv1 = g1[i] / sqrtf(v1[i] + EPS);
            g_bias1[i] = b1[i] - m1[i] * inv1;
            float inv2 = g2[i] / sqrtf(v2[i] + EPS);
            g_c2[i] = b2[i] - m2[i] * inv2;
#pragma unroll
            for (int j = 0; j < 9; j++) g_wdw2f[i * 9 + j] = w_dw2[i * 9 + j] * inv2;
        }
    }
}

// ---------------- stage 1 LIF (vectorized) ----------------------------------
__device__ __forceinline__ float quant01(float m) {
    return rintf(fminf(fmaxf(m, 0.f), 1.f));
}

__global__ void lif1_kernel(const float* __restrict__ x)
{
    size_t idx = ((size_t)blockIdx.x * blockDim.x + threadIdx.x) * 4;
    float4 mem = {0, 0, 0, 0}, sp = {0, 0, 0, 0};
#pragma unroll
    for (int t = 0; t < T_; t++) {
        float4 v = *(const float4*)(x + (size_t)t * STRIDE_T_C + idx);
        mem.x = (mem.x - sp.x * 0.5f) * 0.25f + v.x;  sp.x = quant01(mem.x);
        mem.y = (mem.y - sp.y * 0.5f) * 0.25f + v.y;  sp.y = quant01(mem.y);
        mem.z = (mem.z - sp.z * 0.5f) * 0.25f + v.z;  sp.z = quant01(mem.z);
        mem.w = (mem.w - sp.w * 0.5f) * 0.25f + v.w;  sp.w = quant01(mem.w);
        *(uchar4*)(g_s1 + (size_t)t * STRIDE_T_C + idx) =
            make_uchar4((unsigned char)sp.x, (unsigned char)sp.y,
                        (unsigned char)sp.z, (unsigned char)sp.w);
    }
}

// ---------------- shared GEMM building blocks -------------------------------

#define LDA_PAD 40   // 32 + 8 fp16 pad -> conflict-free ldmatrix
#define LDB_PAD 136  // 128 + 8

__device__ __forceinline__ void ldmx4(uint32_t& r0, uint32_t& r1, uint32_t& r2, uint32_t& r3,
                                      const __half* p)
{
    uint32_t a = (uint32_t)__cvta_generic_to_shared(p);
    asm volatile("ldmatrix.sync.aligned.m8n8.x4.shared.b16 {%0,%1,%2,%3}, [%4];"
                 : "=r"(r0), "=r"(r1), "=r"(r2), "=r"(r3) : "r"(a));
}

__device__ __forceinline__ void ldmx2t(uint32_t& r0, uint32_t& r1, const __half* p)
{
    uint32_t a = (uint32_t)__cvta_generic_to_shared(p);
    asm volatile("ldmatrix.sync.aligned.m8n8.x2.trans.shared.b16 {%0,%1}, [%2];"
                 : "=r"(r0), "=r"(r1) : "r"(a));
}

__device__ __forceinline__ void mma16816h(float* c, uint32_t a0, uint32_t a1, uint32_t a2,
                                          uint32_t a3, uint32_t b0, uint32_t b1)
{
    asm volatile(
        "mma.sync.aligned.m16n8k16.row.col.f32.f16.f16.f32 "
        "{%0,%1,%2,%3}, {%4,%5,%6,%7}, {%8,%9}, {%0,%1,%2,%3};"
        : "+f"(c[0]), "+f"(c[1]), "+f"(c[2]), "+f"(c[3])
        : "r"(a0), "r"(a1), "r"(a2), "r"(a3), "r"(b0), "r"(b1));
}

__device__ __forceinline__ void cvt_spikes(uint4 rB, uint4* dst)
{
    uint32_t out[8];
    uint32_t ws[4] = {rB.x, rB.y, rB.z, rB.w};
#pragma unroll
    for (int q = 0; q < 4; q++) {
        uint32_t w = ws[q];
        out[q * 2 + 0] = ((w)       & 1u) * 0x3C00u | ((w >> 8)  & 1u) * 0x3C000000u;
        out[q * 2 + 1] = ((w >> 16) & 1u) * 0x3C00u | ((w >> 24) & 1u) * 0x3C000000u;
    }
    dst[0] = make_uint4(out[0], out[1], out[2], out[3]);
    dst[1] = make_uint4(out[4], out[5], out[6], out[7]);
}

// ---------------- GEMM1 + fused LIF2 ----------------------------------------
// Grid (8, 4, 16=batch). Each block loops t=0..3, holding LIF2 state (mem2,
// spike bitmask) in registers. Emits uint8 spikes s2 instead of fp32 y1.
__global__ void __launch_bounds__(256) gemm1_kernel()
{
    constexpr int K = C_;
    int b  = blockIdx.z;            // batch 0..15
    int m0 = blockIdx.y * 128;
    int n0 = blockIdx.x * 128;

    __shared__ __align__(16) __half Ahs[128 * LDA_PAD];
    __shared__ __align__(16) __half Als[128 * LDA_PAD];
    __shared__ __align__(16) __half Bs[32 * LDB_PAD];

    int tid  = threadIdx.x;
    int warp = tid >> 5, lane = tid & 31;
    int warp_m = (warp & 1) * 64;
    int warp_n = (warp >> 1) * 32;

    int arow = tid >> 1;
    int acol = (tid & 1) * 16;
    int brow = tid >> 3;
    int bcol = (tid & 7) * 16;

    const __half* pAh = g_W1hi + (size_t)(m0 + arow) * K + acol;
    const __half* pAl = g_W1lo + (size_t)(m0 + arow) * K + acol;

    // LIF2 state: mem (fp32) + spike bitmask, per output element
    float mem2[4][4][4];
    uint32_t spm0 = 0, spm1 = 0;
#pragma unroll
    for (int i = 0; i < 4; i++)
#pragma unroll
        for (int j = 0; j < 4; j++)
#pragma unroll
            for (int q = 0; q < 4; q++) mem2[i][j][q] = 0.f;

#pragma unroll 1
    for (int t = 0; t < T_; t++) {
        int img = t * B_ + b;
        const unsigned char* pB = g_s1 + (size_t)img * K * HW + (size_t)brow * HW + n0 + bcol;

        float accA[4][4][4];
        float accB[4][4][4];
#pragma unroll
        for (int i = 0; i < 4; i++)
#pragma unroll
            for (int j = 0; j < 4; j++)
#pragma unroll
                for (int q = 0; q < 4; q++) { accA[i][j][q] = 0.f; accB[i][j][q] = 0.f; }

        uint4 rAh0, rAh1, rAl0, rAl1, rB;
        rAh0 = *(const uint4*)(pAh);
        rAh1 = *(const uint4*)(pAh + 8);
        rAl0 = *(const uint4*)(pAl);
        rAl1 = *(const uint4*)(pAl + 8);
        rB   = *(const uint4*)(pB);

        if (t > 0) __syncthreads();   // previous t's smem reads done
        {
            *(uint4*)&Ahs[arow * LDA_PAD + acol]     = rAh0;
            *(uint4*)&Ahs[arow * LDA_PAD + acol + 8] = rAh1;
            *(uint4*)&Als[arow * LDA_PAD + acol]     = rAl0;
            *(uint4*)&Als[arow * LDA_PAD + acol + 8] = rAl1;
            cvt_spikes(rB, (uint4*)&Bs[brow * LDB_PAD + bcol]);
        }
        __syncthreads();

        for (int kc = 0; kc < K; kc += 32) {
            bool has_next = (kc + 32 < K);
            if (has_next) {
                rAh0 = *(const uint4*)(pAh + (kc + 32));
                rAh1 = *(const uint4*)(pAh + (kc + 32) + 8);
                rAl0 = *(const uint4*)(pAl + (kc + 32));
                rAl1 = *(const uint4*)(pAl + (kc + 32) + 8);
                rB   = *(const uint4*)(pB + (size_t)(kc + 32) * HW);
            }

#pragma unroll
            for (int ks = 0; ks < 2; ks++) {
                int koff = ks * 16;
                uint32_t bf[4][2];
#pragma unroll
                for (int ni = 0; ni < 4; ni++) {
                    const __half* p = &Bs[(koff + (lane & 15)) * LDB_PAD + warp_n + ni * 8];
                    ldmx2t(bf[ni][0], bf[ni][1], p);
                }
#pragma unroll
                for (int mi = 0; mi < 4; mi++) {
                    int row = warp_m + mi * 16 + (lane & 15);
                    int col = koff + (lane >> 4) * 8;
                    uint32_t a0, a1, a2, a3;
                    ldmx4(a0, a1, a2, a3, &Ahs[row * LDA_PAD + col]);
#pragma unroll
                    for (int ni = 0; ni < 4; ni++)
                        mma16816h(accA[mi][ni], a0, a1, a2, a3, bf[ni][0], bf[ni][1]);
                    ldmx4(a0, a1, a2, a3, &Als[row * LDA_PAD + col]);
#pragma unroll
                    for (int ni = 0; ni < 4; ni++)
                        mma16816h(accB[mi][ni], a0, a1, a2, a3, bf[ni][0], bf[ni][1]);
                }
            }

            if (has_next) {
                __syncthreads();
                *(uint4*)&Ahs[arow * LDA_PAD + acol]     = rAh0;
                *(uint4*)&Ahs[arow * LDA_PAD + acol + 8] = rAh1;
                *(uint4*)&Als[arow * LDA_PAD + acol]     = rAl0;
                *(uint4*)&Als[arow * LDA_PAD + acol + 8] = rAl1;
                cvt_spikes(rB, (uint4*)&Bs[brow * LDB_PAD + bcol]);
                __syncthreads();
            }
        }

        // ---- epilogue: y1 value -> LIF2 -> s2 spikes ----
        unsigned char* Sp = g_s2 + (size_t)img * MED * HW;
#pragma unroll
        for (int mi = 0; mi < 4; mi++) {
            int r0 = m0 + warp_m + mi * 16 + (lane >> 2);
            int r1 = r0 + 8;
            float b0 = g_bias1[r0];
            float b1 = g_bias1[r1];
#pragma unroll
            for (int ni = 0; ni < 4; ni++) {
                int c = n0 + warp_n + ni * 8 + (lane & 3) * 2;
                float y[4];
                y[0] = fmaf(accB[mi][ni][0], LO_INV, accA[mi][ni][0]) + b0;
                y[1] = fmaf(accB[mi][ni][1], LO_INV, accA[mi][ni][1]) + b0;
                y[2] = fmaf(accB[mi][ni][2], LO_INV, accA[mi][ni][2]) + b1;
                y[3] = fmaf(accB[mi][ni][3], LO_INV, accA[mi][ni][3]) + b1;
                unsigned char sb[4];
#pragma unroll
                for (int q = 0; q < 4; q++) {
                    int id = (mi * 4 + ni) * 4 + q;       // 0..63
                    uint32_t& w = (id < 32) ? spm0 : spm1;
                    int bit = id & 31;
                    float sp = (float)((w >> bit) & 1u);
                    float m = (mem2[mi][ni][q] - sp * 0.5f) * 0.25f + y[q];
                    float s = quant01(m);
                    mem2[mi][ni][q] = m;
                    uint32_t su = (uint32_t)s;
                    w = (w & ~(1u << bit)) | (su << bit);
                    sb[q] = (unsigned char)su;
                }
                *(uchar2*)(Sp + (size_t)r0 * HW + c) = make_uchar2(sb[0], sb[1]);
                *(uchar2*)(Sp + (size_t)r1 * HW + c) = make_uchar2(sb[2], sb[3]);
            }
        }
    }
}

// ---------------- GEMM2 (single-pass fp16, double-buffered, R12) ------------
__global__ void __launch_bounds__(256) gemm2_kernel()
{
    constexpr int M = C_, K = MED;
    int img = blockIdx.z;
    const unsigned char* Bp = g_s3 + (size_t)img * K * HW;
    int m0 = blockIdx.y * 128;
    int n0 = blockIdx.x * 128;

    __shared__ __align__(16) __half Ahs[2][128 * LDA_PAD];
    __shared__ __align__(16) __half Bs[2][32 * LDB_PAD];

    int tid  = threadIdx.x;
    int warp = tid >> 5, lane = tid & 31;
    int warp_m = (warp & 1) * 64;
    int warp_n = (warp >> 1) * 32;

    float accA[4][4][4];
#pragma unroll
    for (int i = 0; i < 4; i++)
#pragma unroll
        for (int j = 0; j < 4; j++)
#pragma unroll
            for (int q = 0; q < 4; q++) accA[i][j][q] = 0.f;

    int arow = tid >> 1;
    int acol = (tid & 1) * 16;
    int brow = tid >> 3;
    int bcol = (tid & 7) * 16;

    const __half* pAh = g_W2hi + (size_t)(m0 + arow) * K + acol;
    const unsigned char* pB = Bp + (size_t)brow * HW + n0 + bcol;

    uint4 rAh0, rAh1, rB;

    rAh0 = *(const uint4*)(pAh);
    rAh1 = *(const uint4*)(pAh + 8);
    rB   = *(const uint4*)(pB);
    {
        *(uint4*)&Ahs[0][arow * LDA_PAD + acol]     = rAh0;
        *(uint4*)&Ahs[0][arow * LDA_PAD + acol + 8] = rAh1;
        cvt_spikes(rB, (uint4*)&Bs[0][brow * LDB_PAD + bcol]);
    }
    __syncthreads();

    int buf = 0;
    for (int kc = 0; kc < K; kc += 32) {
        bool has_next = (kc + 32 < K);
        if (has_next) {
            rAh0 = *(const uint4*)(pAh + (kc + 32));
            rAh1 = *(const uint4*)(pAh + (kc + 32) + 8);
            rB   = *(const uint4*)(pB + (size_t)(kc + 32) * HW);
        }

#pragma unroll
        for (int ks = 0; ks < 2; ks++) {
            int koff = ks * 16;
            uint32_t bf[4][2];
#pragma unroll
            for (int ni = 0; ni < 4; ni++) {
                const __half* p = &Bs[buf][(koff + (lane & 15)) * LDB_PAD + warp_n + ni * 8];
                ldmx2t(bf[ni][0], bf[ni][1], p);
            }
#pragma unroll
            for (int mi = 0; mi < 4; mi++) {
                int row = warp_m + mi * 16 + (lane & 15);
                int col = koff + (lane >> 4) * 8;
                uint32_t a0, a1, a2, a3;
                ldmx4(a0, a1, a2, a3, &Ahs[buf][row * LDA_PAD + col]);
#pragma unroll
                for (int ni = 0; ni < 4; ni++)
                    mma16816h(accA[mi][ni], a0, a1, a2, a3, bf[ni][0], bf[ni][1]);
            }
        }

        if (has_next) {
            int nb = buf ^ 1;
            *(uint4*)&Ahs[nb][arow * LDA_PAD + acol]     = rAh0;
            *(uint4*)&Ahs[nb][arow * LDA_PAD + acol + 8] = rAh1;
            cvt_spikes(rB, (uint4*)&Bs[nb][brow * LDB_PAD + bcol]);
            __syncthreads();
            buf = nb;
        }
    }

#pragma unroll
    for (int mi = 0; mi < 4; mi++) {
        int r0 = m0 + warp_m + mi * 16 + (lane >> 2);
        int r1 = r0 + 8;
#pragma unroll
        for (int ni = 0; ni < 4; ni++) {
            int c = n0 + warp_n + ni * 8 + (lane & 3) * 2;
            __half* Cp = g_zv + (size_t)img * M * HW;
            *(__half2*)(Cp + (size_t)r0 * HW + c) =
                __floats2half2_rn(accA[mi][ni][0], accA[mi][ni][1]);
            *(__half2*)(Cp + (size_t)r1 * HW + c) =
                __floats2half2_rn(accA[mi][ni][2], accA[mi][ni][3]);
        }
    }
}

// ---------------- vector-tap 3x3 conv helper (fp16 tile, R12) ---------------
__device__ __forceinline__ void conv_row_h(float conv[4], const __half* rowp,
                                           float wm, float wc, float wp)
{
    __half2 h01 = *(const __half2*)(rowp);
    __half2 h23 = *(const __half2*)(rowp + 2);
    __half2 h45 = *(const __half2*)(rowp + 4);
    float2 f01 = __half22float2(h01);
    float2 f23 = __half22float2(h23);
    float2 f45 = __half22float2(h45);
    conv[0] = fmaf(wm, f01.x, conv[0]); conv[0] = fmaf(wc, f01.y, conv[0]); conv[0] = fmaf(wp, f23.x, conv[0]);
    conv[1] = fmaf(wm, f01.y, conv[1]); conv[1] = fmaf(wc, f23.x, conv[1]); conv[1] = fmaf(wp, f23.y, conv[1]);
    conv[2] = fmaf(wm, f23.x, conv[2]); conv[2] = fmaf(wc, f23.y, conv[2]); conv[2] = fmaf(wp, f45.x, conv[2]);
    conv[3] = fmaf(wm, f23.y, conv[3]); conv[3] = fmaf(wc, f45.x, conv[3]); conv[3] = fmaf(wp, f45.y, conv[3]);
}

// ---------------- mid: s2 spikes -> dw3x3+BN2 -> LIF3 -> s3 -----------------
__global__ void __launch_bounds__(256) mid_kernel()
{
    int bx = blockIdx.x;
    int b  = bx >> 9;
    int c  = bx & 511;
    size_t chanbase = ((size_t)b * MED + c) * HW;

    __shared__ __align__(16) __half tile[2][PTILE];

    int tid = threadIdx.x;
    {
        uint32_t* tz = (uint32_t*)&tile[0][0];
#pragma unroll
        for (int i = 0; i < 5; i++) {
            int p = tid + i * 256;
            if (p < PTILE) tz[p] = 0u;
        }
    }

    float wreg[9];
#pragma unroll
    for (int j = 0; j < 9; j++) wreg[j] = g_wdw2f[c * 9 + j];
    float cc = g_c2[c];

    int h  = tid >> 3;
    int w0 = (tid & 7) * 4;
    int pc = (h + 1) * PW + (w0 + 1);
    int rowbase = h * PW + w0;

    float mem3[4] = {0, 0, 0, 0}, sp3[4] = {0, 0, 0, 0};

    __syncthreads();

#pragma unroll
    for (int t = 0; t < T_; t++) {
        int buf = t & 1;
        size_t base = (size_t)t * STRIDE_T_M + chanbase + (h << 5) + w0;
        uchar4 sv = *(const uchar4*)(g_s2 + base);
        tile[buf][pc + 0] = __ushort_as_half((unsigned short)(sv.x * 0x3C00u));
        tile[buf][pc + 1] = __ushort_as_half((unsigned short)(sv.y * 0x3C00u));
        tile[buf][pc + 2] = __ushort_as_half((unsigned short)(sv.z * 0x3C00u));
        tile[buf][pc + 3] = __ushort_as_half((unsigned short)(sv.w * 0x3C00u));
        __syncthreads();

        float conv[4] = {0.f, 0.f, 0.f, 0.f};
        conv_row_h(conv, &tile[buf][rowbase],          wreg[0], wreg[1], wreg[2]);
        conv_row_h(conv, &tile[buf][rowbase + PW],     wreg[3], wreg[4], wreg[5]);
        conv_row_h(conv, &tile[buf][rowbase + 2 * PW], wreg[6], wreg[7], wreg[8]);

        unsigned char sb[4];
#pragma unroll
        for (int i = 0; i < 4; i++) {
            float y2v = conv[i] + cc;
            mem3[i] = (mem3[i] - sp3[i] * 0.5f) * 0.25f + y2v;
            sp3[i]  = quant01(mem3[i]);
            sb[i]   = (unsigned char)sp3[i];
        }
        *(uchar4*)(g_s3 + base) = make_uchar4(sb[0], sb[1], sb[2], sb[3]);
    }
}

// ---------------- final dw3x3 (fp16 zv tile, fp32 conv, R12) ----------------
__global__ void __launch_bounds__(256) dw3_kernel(float* __restrict__ out)
{
    int plane = blockIdx.x;
    int o = plane & 255;
    size_t base = (size_t)plane * HW;

    __shared__ __align__(16) __half tile[PTILE];

    int tid = threadIdx.x;
    {
        uint32_t* tz = (uint32_t*)&tile[0];
#pragma unroll
        for (int i = 0; i < 3; i++) {
            int p = tid + i * 256;
            if (p < PTILE / 2) tz[p] = 0u;
        }
    }

    float wreg[9];
#pragma unroll
    for (int j = 0; j < 9; j++) wreg[j] = g_wr2f[o * 9 + j];
    float bt = g_Bt[o];

    int h  = tid >> 3;
    int w0 = (tid & 7) * 4;
    int pc = (h + 1) * PW + (w0 + 1);
    int rowbase = h * PW + w0;

    __syncthreads();
    {
        uint2 v = *(const uint2*)(g_zv + base + (h << 5) + w0);
        __half2 p0 = *(__half2*)&v.x;
        __half2 p1 = *(__half2*)&v.y;
        tile[pc + 0] = __low2half(p0);
        tile[pc + 1] = __high2half(p0);
        tile[pc + 2] = __low2half(p1);
        tile[pc + 3] = __high2half(p1);
    }
    __syncthreads();

    float conv[4] = {0.f, 0.f, 0.f, 0.f};
    conv_row_h(conv, &tile[rowbase],          wreg[0], wreg[1], wreg[2]);
    conv_row_h(conv, &tile[rowbase + PW],     wreg[3], wreg[4], wreg[5]);
    conv_row_h(conv, &tile[rowbase + 2 * PW], wreg[6], wreg[7], wreg[8]);

    float4 r = make_float4(conv[0] + bt, conv[1] + bt, conv[2] + bt, conv[3] + bt);
    *(float4*)(out + base + (h << 5) + w0) = r;
}

// ---------------- launch ---------------------------------------------------
extern "C" void kernel_launch(void* const* d_in, const int* in_sizes, int n_in,
                              void* d_out, int out_size)
{
    const float* x      = (const float*)d_in[0];
    const float* w_pw1  = (const float*)d_in[1];
    const float* g1 = (const float*)d_in[2];
    const float* b1 = (const float*)d_in[3];
    const float* m1 = (const float*)d_in[4];
    const float* v1 = (const float*)d_in[5];
    const float* w_dw2  = (const float*)d_in[6];
    const float* g2 = (const float*)d_in[7];
    const float* b2 = (const float*)d_in[8];
    const float* m2 = (const float*)d_in[9];
    const float* v2 = (const float*)d_in[10];
    const float* gp = (const float*)d_in[11];
    const float* bp = (const float*)d_in[12];
    const float* mp = (const float*)d_in[13];
    const float* vp = (const float*)d_in[14];
    const float* w_rep1 = (const float*)d_in[15];
    const float* w_rep2 = (const float*)d_in[16];
    const float* g3 = (const float*)d_in[17];
    const float* b3 = (const float*)d_in[18];
    const float* m3 = (const float*)d_in[19];
    const float* v3 = (const float*)d_in[20];
    float* out = (float*)d_out;

    prep_all<<<1025, 256>>>(w_pw1, g1, b1, m1, v1, w_dw2, g2, b2, m2, v2,
                            gp, bp, mp, vp, w_rep1, w_rep2, g3, b3, m3, v3);

    lif1_kernel<<<(int)(STRIDE_T_C / 1024), 256>>>(x);

    gemm1_kernel<<<dim3(8, 4, B_), 256>>>();                    // fused LIF2

    mid_kernel<<<B_ * MED, 256>>>();                            // 8192 blocks

    gemm2_kernel<<<dim3(HW / 128, C_ / 128, IMGS), 256>>>();    // (8,2,64)

    dw3_kernel<<<IMGS * C_, 256>>>(out);                        // 16384 blocks
}

// round 16
// speedup vs baseline: 1.0355x; 1.0355x over previous
#include <cuda_runtime.h>
#include <cuda_fp16.h>
#include <cstdint>

#define EPS 1e-5f

// Problem dims
constexpr int T_   = 4;
constexpr int B_   = 16;
constexpr int C_   = 256;
constexpr int MED  = 512;
constexpr int HW   = 1024;   // 32*32
constexpr int IMGS = 64;     // T*B

constexpr size_t N_X  = (size_t)T_ * B_ * C_  * HW;
constexpr size_t N_Y1 = (size_t)T_ * B_ * MED * HW;
constexpr size_t STRIDE_T_C = (size_t)B_ * C_  * HW;
constexpr size_t STRIDE_T_M = (size_t)B_ * MED * HW;

constexpr float LO_SCALE   = 2048.0f;          // 2^11
constexpr float LO_INV     = 1.0f / 2048.0f;

// padded spatial tile for branch-free 3x3 conv (R12 layout)
#define PH 34
#define PW 36
#define PTILE (PH * PW)   // 1224

// ---------------- scratch (device globals) ---------------------------------
__device__ unsigned char g_s1[N_X];     // stage1 spikes  [T,B,C,HW]
__device__ unsigned char g_s2[N_Y1];    // stage2 spikes  [T,B,MED,HW] (fused LIF2)
__device__ unsigned char g_s3[N_Y1];    // stage3 spikes  [T,B,MED,HW]
__device__ __half        g_zv[N_X];     // stage3 1x1 conv variable part (fp16)

__device__ __half g_W1hi[MED * C_];
__device__ __half g_W1lo[MED * C_];     // (w-hi)*2^11
__device__ __half g_W2hi[C_ * MED];     // single-pass fp16 (no threshold downstream)
__device__ float g_bias1[MED];          // b1 - m1*inv1
__device__ float g_wdw2f[MED * 9];      // w_dw2 * inv2(c)
__device__ float g_c2[MED];             // b2 - m2*inv2
__device__ float g_wr2f[C_ * 9];        // w_rep2 * inv3(o)
__device__ float g_Bt[C_];              // total bias for final dw+BN3

// ---------------- merged prep kernel ---------------------------------------
__device__ __forceinline__ void split2h(float w, __half& hi, __half& lo)
{
    hi = __float2half_rn(w);
    float r = w - __half2float(hi);
    lo = __float2half_rn(r * LO_SCALE);
}

__global__ void prep_all(const float* __restrict__ w_pw1,
                         const float* __restrict__ g1, const float* __restrict__ b1,
                         const float* __restrict__ m1, const float* __restrict__ v1,
                         const float* __restrict__ w_dw2,
                         const float* __restrict__ g2, const float* __restrict__ b2,
                         const float* __restrict__ m2, const float* __restrict__ v2,
                         const float* __restrict__ gp, const float* __restrict__ bp,
                         const float* __restrict__ mp, const float* __restrict__ vp,
                         const float* __restrict__ w_rep1, const float* __restrict__ w_rep2,
                         const float* __restrict__ g3, const float* __restrict__ b3,
                         const float* __restrict__ m3, const float* __restrict__ v3)
{
    int bx = blockIdx.x;
    int tid = threadIdx.x;   // 256

    if (bx < 512) {
        int o = bx, k = tid;
        float inv1 = g1[o] / sqrtf(v1[o] + EPS);
        float w = w_pw1[o * C_ + k] * inv1;
        __half hi, lo;
        split2h(w, hi, lo);
        g_W1hi[o * C_ + k] = hi;
        g_W1lo[o * C_ + k] = lo;
    } else if (bx < 768) {
        int o = bx - 512;
#pragma unroll
        for (int kk = 0; kk < 2; kk++) {
            int k = tid + kk * 256;
            float invp = gp[k] / sqrtf(vp[k] + EPS);
            float w = w_rep1[o * MED + k] * invp;
            g_W2hi[o * MED + k] = __float2half_rn(w);
        }
    } else if (bx < 1024) {
        int o = bx - 768;
        float p = 0.f;
#pragma unroll
        for (int kk = 0; kk < 2; kk++) {
            int k = tid + kk * 256;
            float invp = gp[k] / sqrtf(vp[k] + EPS);
            float cpk = bp[k] - mp[k] * invp;
            p += w_rep1[o * MED + k] * cpk;
        }
        __shared__ float red[256];
        red[tid] = p;
        __syncthreads();
        for (int s = 128; s > 0; s >>= 1) {
            if (tid < s) red[tid] += red[tid + s];
            __syncthreads();
        }
        if (tid == 0) {
            float cb = red[0];
            float inv3 = g3[o] / sqrtf(v3[o] + EPS);
            float sw = 0.f;
#pragma unroll
            for (int j = 0; j < 9; j++) {
                float wv = w_rep2[o * 9 + j];
                g_wr2f[o * 9 + j] = wv * inv3;
                sw += wv;
            }
            g_Bt[o] = (b3[o] - m3[o] * inv3) + inv3 * cb * sw;
        }
    } else {
#pragma unroll
        for (int kk = 0; kk < 2; kk++) {
            int i = tid + kk * 256;
            float inv1 = g1[i] / sqrtf(v1[i] + EPS);
            g_bias1[i] = b1[i] - m1[i] * inv1;
            float inv2 = g2[i] / sqrtf(v2[i] + EPS);
            g_c2[i] = b2[i] - m2[i] * inv2;
#pragma unroll
            for (int j = 0; j < 9; j++) g_wdw2f[i * 9 + j] = w_dw2[i * 9 + j] * inv2;
        }
    }
}

// ---------------- stage 1 LIF (vectorized) ----------------------------------
__device__ __forceinline__ float quant01(float m) {
    return rintf(fminf(fmaxf(m, 0.f), 1.f));
}

__global__ void lif1_kernel(const float* __restrict__ x)
{
    size_t idx = ((size_t)blockIdx.x * blockDim.x + threadIdx.x) * 4;
    float4 mem = {0, 0, 0, 0}, sp = {0, 0, 0, 0};
#pragma unroll
    for (int t = 0; t < T_; t++) {
        float4 v = *(const float4*)(x + (size_t)t * STRIDE_T_C + idx);
        mem.x = (mem.x - sp.x * 0.5f) * 0.25f + v.x;  sp.x = quant01(mem.x);
        mem.y = (mem.y - sp.y * 0.5f) * 0.25f + v.y;  sp.y = quant01(mem.y);
        mem.z = (mem.z - sp.z * 0.5f) * 0.25f + v.z;  sp.z = quant01(mem.z);
        mem.w = (mem.w - sp.w * 0.5f) * 0.25f + v.w;  sp.w = quant01(mem.w);
        *(uchar4*)(g_s1 + (size_t)t * STRIDE_T_C + idx) =
            make_uchar4((unsigned char)sp.x, (unsigned char)sp.y,
                        (unsigned char)sp.z, (unsigned char)sp.w);
    }
}

// ---------------- shared GEMM building blocks -------------------------------

#define LDA_PAD 40   // 32 + 8 fp16 pad -> conflict-free ldmatrix
#define LDB_PAD 136  // 128 + 8

__device__ __forceinline__ void ldmx4(uint32_t& r0, uint32_t& r1, uint32_t& r2, uint32_t& r3,
                                      const __half* p)
{
    uint32_t a = (uint32_t)__cvta_generic_to_shared(p);
    asm volatile("ldmatrix.sync.aligned.m8n8.x4.shared.b16 {%0,%1,%2,%3}, [%4];"
                 : "=r"(r0), "=r"(r1), "=r"(r2), "=r"(r3) : "r"(a));
}

__device__ __forceinline__ void ldmx2t(uint32_t& r0, uint32_t& r1, const __half* p)
{
    uint32_t a = (uint32_t)__cvta_generic_to_shared(p);
    asm volatile("ldmatrix.sync.aligned.m8n8.x2.trans.shared.b16 {%0,%1}, [%2];"
                 : "=r"(r0), "=r"(r1) : "r"(a));
}

__device__ __forceinline__ void mma16816h(float* c, uint32_t a0, uint32_t a1, uint32_t a2,
                                          uint32_t a3, uint32_t b0, uint32_t b1)
{
    asm volatile(
        "mma.sync.aligned.m16n8k16.row.col.f32.f16.f16.f32 "
        "{%0,%1,%2,%3}, {%4,%5,%6,%7}, {%8,%9}, {%0,%1,%2,%3};"
        : "+f"(c[0]), "+f"(c[1]), "+f"(c[2]), "+f"(c[3])
        : "r"(a0), "r"(a1), "r"(a2), "r"(a3), "r"(b0), "r"(b1));
}

__device__ __forceinline__ void cvt_spikes(uint4 rB, uint4* dst)
{
    uint32_t out[8];
    uint32_t ws[4] = {rB.x, rB.y, rB.z, rB.w};
#pragma unroll
    for (int q = 0; q < 4; q++) {
        uint32_t w = ws[q];
        out[q * 2 + 0] = ((w)       & 1u) * 0x3C00u | ((w >> 8)  & 1u) * 0x3C000000u;
        out[q * 2 + 1] = ((w >> 16) & 1u) * 0x3C00u | ((w >> 24) & 1u) * 0x3C000000u;
    }
    dst[0] = make_uint4(out[0], out[1], out[2], out[3]);
    dst[1] = make_uint4(out[4], out[5], out[6], out[7]);
}

// ---------------- GEMM1 + fused LIF2 (M-tile 64, grid 8x8x16) ---------------
// Each block: M=64, N=128, K=256; t-loop with LIF2 state in registers.
// 8 warps in 2(m)x4(n), warp tile 32x32. Emits uint8 spikes s2.
__global__ void __launch_bounds__(256) gemm1_kernel()
{
    constexpr int K = C_;
    int b  = blockIdx.z;            // batch 0..15
    int m0 = blockIdx.y * 64;
    int n0 = blockIdx.x * 128;

    __shared__ __align__(16) __half Ahs[64 * LDA_PAD];
    __shared__ __align__(16) __half Als[64 * LDA_PAD];
    __shared__ __align__(16) __half Bs[32 * LDB_PAD];

    int tid  = threadIdx.x;
    int warp = tid >> 5, lane = tid & 31;
    int warp_m = (warp & 1) * 32;   // 2 warps along M
    int warp_n = (warp >> 1) * 32;  // 4 warps along N

    // A: 64 rows x 32 halfs per chunk; 4 threads/row of 8 halfs (16B)
    int arow = tid >> 2;            // 0..63
    int acol = (tid & 3) * 8;       // 0,8,16,24
    // B: 32 rows x 128 px; uint4 per thread
    int brow = tid >> 3;            // 0..31
    int bcol = (tid & 7) * 16;

    const __half* pAh = g_W1hi + (size_t)(m0 + arow) * K + acol;
    const __half* pAl = g_W1lo + (size_t)(m0 + arow) * K + acol;

    // LIF2 state: mem (fp32) + 32-bit spike mask (2*4*4 = 32 outputs)
    float mem2[2][4][4];
    uint32_t spm = 0;
#pragma unroll
    for (int i = 0; i < 2; i++)
#pragma unroll
        for (int j = 0; j < 4; j++)
#pragma unroll
            for (int q = 0; q < 4; q++) mem2[i][j][q] = 0.f;

#pragma unroll 1
    for (int t = 0; t < T_; t++) {
        int img = t * B_ + b;
        const unsigned char* pB = g_s1 + (size_t)img * K * HW + (size_t)brow * HW + n0 + bcol;

        float accA[2][4][4];
        float accB[2][4][4];
#pragma unroll
        for (int i = 0; i < 2; i++)
#pragma unroll
            for (int j = 0; j < 4; j++)
#pragma unroll
                for (int q = 0; q < 4; q++) { accA[i][j][q] = 0.f; accB[i][j][q] = 0.f; }

        uint4 rAh, rAl, rB;
        rAh = *(const uint4*)(pAh);
        rAl = *(const uint4*)(pAl);
        rB  = *(const uint4*)(pB);

        if (t > 0) __syncthreads();   // previous t's smem reads done
        {
            *(uint4*)&Ahs[arow * LDA_PAD + acol] = rAh;
            *(uint4*)&Als[arow * LDA_PAD + acol] = rAl;
            cvt_spikes(rB, (uint4*)&Bs[brow * LDB_PAD + bcol]);
        }
        __syncthreads();

        for (int kc = 0; kc < K; kc += 32) {
            bool has_next = (kc + 32 < K);
            if (has_next) {
                rAh = *(const uint4*)(pAh + (kc + 32));
                rAl = *(const uint4*)(pAl + (kc + 32));
                rB  = *(const uint4*)(pB + (size_t)(kc + 32) * HW);
            }

#pragma unroll
            for (int ks = 0; ks < 2; ks++) {
                int koff = ks * 16;
                uint32_t bf[4][2];
#pragma unroll
                for (int ni = 0; ni < 4; ni++) {
                    const __half* p = &Bs[(koff + (lane & 15)) * LDB_PAD + warp_n + ni * 8];
                    ldmx2t(bf[ni][0], bf[ni][1], p);
                }
#pragma unroll
                for (int mi = 0; mi < 2; mi++) {
                    int row = warp_m + mi * 16 + (lane & 15);
                    int col = koff + (lane >> 4) * 8;
                    uint32_t a0, a1, a2, a3;
                    ldmx4(a0, a1, a2, a3, &Ahs[row * LDA_PAD + col]);
#pragma unroll
                    for (int ni = 0; ni < 4; ni++)
                        mma16816h(accA[mi][ni], a0, a1, a2, a3, bf[ni][0], bf[ni][1]);
                    ldmx4(a0, a1, a2, a3, &Als[row * LDA_PAD + col]);
#pragma unroll
                    for (int ni = 0; ni < 4; ni++)
                        mma16816h(accB[mi][ni], a0, a1, a2, a3, bf[ni][0], bf[ni][1]);
                }
            }

            if (has_next) {
                __syncthreads();
                *(uint4*)&Ahs[arow * LDA_PAD + acol] = rAh;
                *(uint4*)&Als[arow * LDA_PAD + acol] = rAl;
                cvt_spikes(rB, (uint4*)&Bs[brow * LDB_PAD + bcol]);
                __syncthreads();
            }
        }

        // ---- epilogue: y1 value -> LIF2 -> s2 spikes ----
        unsigned char* Sp = g_s2 + (size_t)img * MED * HW;
#pragma unroll
        for (int mi = 0; mi < 2; mi++) {
            int r0 = m0 + warp_m + mi * 16 + (lane >> 2);
            int r1 = r0 + 8;
            float b0 = g_bias1[r0];
            float b1 = g_bias1[r1];
#pragma unroll
            for (int ni = 0; ni < 4; ni++) {
                int c = n0 + warp_n + ni * 8 + (lane & 3) * 2;
                float y[4];
                y[0] = fmaf(accB[mi][ni][0], LO_INV, accA[mi][ni][0]) + b0;
                y[1] = fmaf(accB[mi][ni][1], LO_INV, accA[mi][ni][1]) + b0;
                y[2] = fmaf(accB[mi][ni][2], LO_INV, accA[mi][ni][2]) + b1;
                y[3] = fmaf(accB[mi][ni][3], LO_INV, accA[mi][ni][3]) + b1;
                unsigned char sb[4];
#pragma unroll
                for (int q = 0; q < 4; q++) {
                    int bit = (mi * 4 + ni) * 4 + q;      // 0..31
                    float sp = (float)((spm >> bit) & 1u);
                    float m = (mem2[mi][ni][q] - sp * 0.5f) * 0.25f + y[q];
                    float s = quant01(m);
                    mem2[mi][ni][q] = m;
                    uint32_t su = (uint32_t)s;
                    spm = (spm & ~(1u << bit)) | (su << bit);
                    sb[q] = (unsigned char)su;
                }
                *(uchar2*)(Sp + (size_t)r0 * HW + c) = make_uchar2(sb[0], sb[1]);
                *(uchar2*)(Sp + (size_t)r1 * HW + c) = make_uchar2(sb[2], sb[3]);
            }
        }
    }
}

// ---------------- GEMM2 (single-pass fp16, double-buffered, R12) ------------
__global__ void __launch_bounds__(256) gemm2_kernel()
{
    constexpr int M = C_, K = MED;
    int img = blockIdx.z;
    const unsigned char* Bp = g_s3 + (size_t)img * K * HW;
    int m0 = blockIdx.y * 128;
    int n0 = blockIdx.x * 128;

    __shared__ __align__(16) __half Ahs[2][128 * LDA_PAD];
    __shared__ __align__(16) __half Bs[2][32 * LDB_PAD];

    int tid  = threadIdx.x;
    int warp = tid >> 5, lane = tid & 31;
    int warp_m = (warp & 1) * 64;
    int warp_n = (warp >> 1) * 32;

    float accA[4][4][4];
#pragma unroll
    for (int i = 0; i < 4; i++)
#pragma unroll
        for (int j = 0; j < 4; j++)
#pragma unroll
            for (int q = 0; q < 4; q++) accA[i][j][q] = 0.f;

    int arow = tid >> 1;
    int acol = (tid & 1) * 16;
    int brow = tid >> 3;
    int bcol = (tid & 7) * 16;

    const __half* pAh = g_W2hi + (size_t)(m0 + arow) * K + acol;
    const unsigned char* pB = Bp + (size_t)brow * HW + n0 + bcol;

    uint4 rAh0, rAh1, rB;

    rAh0 = *(const uint4*)(pAh);
    rAh1 = *(const uint4*)(pAh + 8);
    rB   = *(const uint4*)(pB);
    {
        *(uint4*)&Ahs[0][arow * LDA_PAD + acol]     = rAh0;
        *(uint4*)&Ahs[0][arow * LDA_PAD + acol + 8] = rAh1;
        cvt_spikes(rB, (uint4*)&Bs[0][brow * LDB_PAD + bcol]);
    }
    __syncthreads();

    int buf = 0;
    for (int kc = 0; kc < K; kc += 32) {
        bool has_next = (kc + 32 < K);
        if (has_next) {
            rAh0 = *(const uint4*)(pAh + (kc + 32));
            rAh1 = *(const uint4*)(pAh + (kc + 32) + 8);
            rB   = *(const uint4*)(pB + (size_t)(kc + 32) * HW);
        }

#pragma unroll
        for (int ks = 0; ks < 2; ks++) {
            int koff = ks * 16;
            uint32_t bf[4][2];
#pragma unroll
            for (int ni = 0; ni < 4; ni++) {
                const __half* p = &Bs[buf][(koff + (lane & 15)) * LDB_PAD + warp_n + ni * 8];
                ldmx2t(bf[ni][0], bf[ni][1], p);
            }
#pragma unroll
            for (int mi = 0; mi < 4; mi++) {
                int row = warp_m + mi * 16 + (lane & 15);
                int col = koff + (lane >> 4) * 8;
                uint32_t a0, a1, a2, a3;
                ldmx4(a0, a1, a2, a3, &Ahs[buf][row * LDA_PAD + col]);
#pragma unroll
                for (int ni = 0; ni < 4; ni++)
                    mma16816h(accA[mi][ni], a0, a1, a2, a3, bf[ni][0], bf[ni][1]);
            }
        }

        if (has_next) {
            int nb = buf ^ 1;
            *(uint4*)&Ahs[nb][arow * LDA_PAD + acol]     = rAh0;
            *(uint4*)&Ahs[nb][arow * LDA_PAD + acol + 8] = rAh1;
            cvt_spikes(rB, (uint4*)&Bs[nb][brow * LDB_PAD + bcol]);
            __syncthreads();
            buf = nb;
        }
    }

#pragma unroll
    for (int mi = 0; mi < 4; mi++) {
        int r0 = m0 + warp_m + mi * 16 + (lane >> 2);
        int r1 = r0 + 8;
#pragma unroll
        for (int ni = 0; ni < 4; ni++) {
            int c = n0 + warp_n + ni * 8 + (lane & 3) * 2;
            __half* Cp = g_zv + (size_t)img * M * HW;
            *(__half2*)(Cp + (size_t)r0 * HW + c) =
                __floats2half2_rn(accA[mi][ni][0], accA[mi][ni][1]);
            *(__half2*)(Cp + (size_t)r1 * HW + c) =
                __floats2half2_rn(accA[mi][ni][2], accA[mi][ni][3]);
        }
    }
}

// ---------------- vector-tap 3x3 conv helper (fp16 tile, R12) ---------------
__device__ __forceinline__ void conv_row_h(float conv[4], const __half* rowp,
                                           float wm, float wc, float wp)
{
    __half2 h01 = *(const __half2*)(rowp);
    __half2 h23 = *(const __half2*)(rowp + 2);
    __half2 h45 = *(const __half2*)(rowp + 4);
    float2 f01 = __half22float2(h01);
    float2 f23 = __half22float2(h23);
    float2 f45 = __half22float2(h45);
    conv[0] = fmaf(wm, f01.x, conv[0]); conv[0] = fmaf(wc, f01.y, conv[0]); conv[0] = fmaf(wp, f23.x, conv[0]);
    conv[1] = fmaf(wm, f01.y, conv[1]); conv[1] = fmaf(wc, f23.x, conv[1]); conv[1] = fmaf(wp, f23.y, conv[1]);
    conv[2] = fmaf(wm, f23.x, conv[2]); conv[2] = fmaf(wc, f23.y, conv[2]); conv[2] = fmaf(wp, f45.x, conv[2]);
    conv[3] = fmaf(wm, f23.y, conv[3]); conv[3] = fmaf(wc, f45.x, conv[3]); conv[3] = fmaf(wp, f45.y, conv[3]);
}

// ---------------- mid: s2 spikes -> dw3x3+BN2 -> LIF3 -> s3 -----------------
__global__ void __launch_bounds__(256) mid_kernel()
{
    int bx = blockIdx.x;
    int b  = bx >> 9;
    int c  = bx & 511;
    size_t chanbase = ((size_t)b * MED + c) * HW;

    __shared__ __align__(16) __half tile[2][PTILE];

    int tid = threadIdx.x;
    {
        uint32_t* tz = (uint32_t*)&tile[0][0];
#pragma unroll
        for (int i = 0; i < 5; i++) {
            int p = tid + i * 256;
            if (p < PTILE) tz[p] = 0u;
        }
    }

    float wreg[9];
#pragma unroll
    for (int j = 0; j < 9; j++) wreg[j] = g_wdw2f[c * 9 + j];
    float cc = g_c2[c];

    int h  = tid >> 3;
    int w0 = (tid & 7) * 4;
    int pc = (h + 1) * PW + (w0 + 1);
    int rowbase = h * PW + w0;

    float mem3[4] = {0, 0, 0, 0}, sp3[4] = {0, 0, 0, 0};

    __syncthreads();

#pragma unroll
    for (int t = 0; t < T_; t++) {
        int buf = t & 1;
        size_t base = (size_t)t * STRIDE_T_M + chanbase + (h << 5) + w0;
        uchar4 sv = *(const uchar4*)(g_s2 + base);
        tile[buf][pc + 0] = __ushort_as_half((unsigned short)(sv.x * 0x3C00u));
        tile[buf][pc + 1] = __ushort_as_half((unsigned short)(sv.y * 0x3C00u));
        tile[buf][pc + 2] = __ushort_as_half((unsigned short)(sv.z * 0x3C00u));
        tile[buf][pc + 3] = __ushort_as_half((unsigned short)(sv.w * 0x3C00u));
        __syncthreads();

        float conv[4] = {0.f, 0.f, 0.f, 0.f};
        conv_row_h(conv, &tile[buf][rowbase],          wreg[0], wreg[1], wreg[2]);
        conv_row_h(conv, &tile[buf][rowbase + PW],     wreg[3], wreg[4], wreg[5]);
        conv_row_h(conv, &tile[buf][rowbase + 2 * PW], wreg[6], wreg[7], wreg[8]);

        unsigned char sb[4];
#pragma unroll
        for (int i = 0; i < 4; i++) {
            float y2v = conv[i] + cc;
            mem3[i] = (mem3[i] - sp3[i] * 0.5f) * 0.25f + y2v;
            sp3[i]  = quant01(mem3[i]);
            sb[i]   = (unsigned char)sp3[i];
        }
        *(uchar4*)(g_s3 + base) = make_uchar4(sb[0], sb[1], sb[2], sb[3]);
    }
}

// ---------------- final dw3x3 (fp16 zv tile, fp32 conv, R12) ----------------
__global__ void __launch_bounds__(256) dw3_kernel(float* __restrict__ out)
{
    int plane = blockIdx.x;
    int o = plane & 255;
    size_t base = (size_t)plane * HW;

    __shared__ __align__(16) __half tile[PTILE];

    int tid = threadIdx.x;
    {
        uint32_t* tz = (uint32_t*)&tile[0];
#pragma unroll
        for (int i = 0; i < 3; i++) {
            int p = tid + i * 256;
            if (p < PTILE / 2) tz[p] = 0u;
        }
    }

    float wreg[9];
#pragma unroll
    for (int j = 0; j < 9; j++) wreg[j] = g_wr2f[o * 9 + j];
    float bt = g_Bt[o];

    int h  = tid >> 3;
    int w0 = (tid & 7) * 4;
    int pc = (h + 1) * PW + (w0 + 1);
    int rowbase = h * PW + w0;

    __syncthreads();
    {
        uint2 v = *(const uint2*)(g_zv + base + (h << 5) + w0);
        __half2 p0 = *(__half2*)&v.x;
        __half2 p1 = *(__half2*)&v.y;
        tile[pc + 0] = __low2half(p0);
        tile[pc + 1] = __high2half(p0);
        tile[pc + 2] = __low2half(p1);
        tile[pc + 3] = __high2half(p1);
    }
    __syncthreads();

    float conv[4] = {0.f, 0.f, 0.f, 0.f};
    conv_row_h(conv, &tile[rowbase],          wreg[0], wreg[1], wreg[2]);
    conv_row_h(conv, &tile[rowbase + PW],     wreg[3], wreg[4], wreg[5]);
    conv_row_h(conv, &tile[rowbase + 2 * PW], wreg[6], wreg[7], wreg[8]);

    float4 r = make_float4(conv[0] + bt, conv[1] + bt, conv[2] + bt, conv[3] + bt);
    *(float4*)(out + base + (h << 5) + w0) = r;
}

// ---------------- launch ---------------------------------------------------
extern "C" void kernel_launch(void* const* d_in, const int* in_sizes, int n_in,
                              void* d_out, int out_size)
{
    const float* x      = (const float*)d_in[0];
    const float* w_pw1  = (const float*)d_in[1];
    const float* g1 = (const float*)d_in[2];
    const float* b1 = (const float*)d_in[3];
    const float* m1 = (const float*)d_in[4];
    const float* v1 = (const float*)d_in[5];
    const float* w_dw2  = (const float*)d_in[6];
    const float* g2 = (const float*)d_in[7];
    const float* b2 = (const float*)d_in[8];
    const float* m2 = (const float*)d_in[9];
    const float* v2 = (const float*)d_in[10];
    const float* gp = (const float*)d_in[11];
    const float* bp = (const float*)d_in[12];
    const float* mp = (const float*)d_in[13];
    const float* vp = (const float*)d_in[14];
    const float* w_rep1 = (const float*)d_in[15];
    const float* w_rep2 = (const float*)d_in[16];
    const float* g3 = (const float*)d_in[17];
    const float* b3 = (const float*)d_in[18];
    const float* m3 = (const float*)d_in[19];
    const float* v3 = (const float*)d_in[20];
    float* out = (float*)d_out;

    prep_all<<<1025, 256>>>(w_pw1, g1, b1, m1, v1, w_dw2, g2, b2, m2, v2,
                            gp, bp, mp, vp, w_rep1, w_rep2, g3, b3, m3, v3);

    lif1_kernel<<<(int)(STRIDE_T_C / 1024), 256>>>(x);

    gemm1_kernel<<<dim3(8, 8, B_), 256>>>();                    // fused LIF2, M-tile 64

    mid_kernel<<<B_ * MED, 256>>>();                            // 8192 blocks

    gemm2_kernel<<<dim3(HW / 128, C_ / 128, IMGS), 256>>>();    // (8,2,64)

    dw3_kernel<<<IMGS * C_, 256>>>(out);                        // 16384 blocks
}

// round 17
// speedup vs baseline: 1.1559x; 1.1163x over previous
#include <cuda_runtime.h>
#include <cuda_fp16.h>
#include <cstdint>

#define EPS 1e-5f

// Problem dims
constexpr int T_   = 4;
constexpr int B_   = 16;
constexpr int C_   = 256;
constexpr int MED  = 512;
constexpr int HW   = 1024;   // 32*32
constexpr int IMGS = 64;     // T*B

constexpr size_t N_X  = (size_t)T_ * B_ * C_  * HW;
constexpr size_t N_Y1 = (size_t)T_ * B_ * MED * HW;
constexpr size_t STRIDE_T_C = (size_t)B_ * C_  * HW;
constexpr size_t STRIDE_T_M = (size_t)B_ * MED * HW;

constexpr float LO_SCALE   = 2048.0f;          // 2^11
constexpr float LO_INV     = 1.0f / 2048.0f;

// padded spatial tile for branch-free 3x3 conv
#define PH 34
#define PW 36
#define PTILE (PH * PW)   // 1224

// ---------------- scratch (device globals) ---------------------------------
__device__ unsigned char g_s1[N_X];     // stage1 spikes  [T,B,C,HW]
__device__ float         g_y1[N_Y1];    // stage1 output  [T,B,MED,HW]
__device__ unsigned char g_s3[N_Y1];    // stage3 spikes  [T,B,MED,HW]
__device__ __half        g_zv[N_X];     // stage3 1x1 conv variable part (fp16)

__device__ __half g_W1hi[MED * C_];
__device__ __half g_W1lo[MED * C_];     // (w-hi)*2^11
__device__ __half g_W2hi[C_ * MED];     // single-pass fp16 (no threshold downstream)
__device__ float g_bias1[MED];          // b1 - m1*inv1
__device__ float g_wdw2f[MED * 9];      // w_dw2 * inv2(c)
__device__ float g_c2[MED];             // b2 - m2*inv2
__device__ float g_wr2f[C_ * 9];        // w_rep2 * inv3(o)
__device__ float g_Bt[C_];              // total bias for final dw+BN3

// ---------------- merged prep kernel ---------------------------------------
__device__ __forceinline__ void split2h(float w, __half& hi, __half& lo)
{
    hi = __float2half_rn(w);
    float r = w - __half2float(hi);
    lo = __float2half_rn(r * LO_SCALE);
}

__global__ void prep_all(const float* __restrict__ w_pw1,
                         const float* __restrict__ g1, const float* __restrict__ b1,
                         const float* __restrict__ m1, const float* __restrict__ v1,
                         const float* __restrict__ w_dw2,
                         const float* __restrict__ g2, const float* __restrict__ b2,
                         const float* __restrict__ m2, const float* __restrict__ v2,
                         const float* __restrict__ gp, const float* __restrict__ bp,
                         const float* __restrict__ mp, const float* __restrict__ vp,
                         const float* __restrict__ w_rep1, const float* __restrict__ w_rep2,
                         const float* __restrict__ g3, const float* __restrict__ b3,
                         const float* __restrict__ m3, const float* __restrict__ v3)
{
    int bx = blockIdx.x;
    int tid = threadIdx.x;   // 256

    if (bx < 512) {
        int o = bx, k = tid;
        float inv1 = g1[o] / sqrtf(v1[o] + EPS);
        float w = w_pw1[o * C_ + k] * inv1;
        __half hi, lo;
        split2h(w, hi, lo);
        g_W1hi[o * C_ + k] = hi;
        g_W1lo[o * C_ + k] = lo;
    } else if (bx < 768) {
        int o = bx - 512;
#pragma unroll
        for (int kk = 0; kk < 2; kk++) {
            int k = tid + kk * 256;
            float invp = gp[k] / sqrtf(vp[k] + EPS);
            float w = w_rep1[o * MED + k] * invp;
            g_W2hi[o * MED + k] = __float2half_rn(w);
        }
    } else if (bx < 1024) {
        int o = bx - 768;
        float p = 0.f;
#pragma unroll
        for (int kk = 0; kk < 2; kk++) {
            int k = tid + kk * 256;
            float invp = gp[k] / sqrtf(vp[k] + EPS);
            float cpk = bp[k] - mp[k] * invp;
            p += w_rep1[o * MED + k] * cpk;
        }
        __shared__ float red[256];
        red[tid] = p;
        __syncthreads();
        for (int s = 128; s > 0; s >>= 1) {
            if (tid < s) red[tid] += red[tid + s];
            __syncthreads();
        }
        if (tid == 0) {
            float cb = red[0];
            float inv3 = g3[o] / sqrtf(v3[o] + EPS);
            float sw = 0.f;
#pragma unroll
            for (int j = 0; j < 9; j++) {
                float wv = w_rep2[o * 9 + j];
                g_wr2f[o * 9 + j] = wv * inv3;
                sw += wv;
            }
            g_Bt[o] = (b3[o] - m3[o] * inv3) + inv3 * cb * sw;
        }
    } else {
#pragma unroll
        for (int kk = 0; kk < 2; kk++) {
            int i = tid + kk * 256;
            float inv1 = g1[i] / sqrtf(v1[i] + EPS);
            g_bias1[i] = b1[i] - m1[i] * inv1;
            float inv2 = g2[i] / sqrtf(v2[i] + EPS);
            g_c2[i] = b2[i] - m2[i] * inv2;
#pragma unroll
            for (int j = 0; j < 9; j++) g_wdw2f[i * 9 + j] = w_dw2[i * 9 + j] * inv2;
        }
    }
}

// ---------------- stage 1 LIF (vectorized) ----------------------------------
__device__ __forceinline__ float quant01(float m) {
    return rintf(fminf(fmaxf(m, 0.f), 1.f));
}

__global__ void lif1_kernel(const float* __restrict__ x)
{
    size_t idx = ((size_t)blockIdx.x * blockDim.x + threadIdx.x) * 4;
    float4 mem = {0, 0, 0, 0}, sp = {0, 0, 0, 0};
#pragma unroll
    for (int t = 0; t < T_; t++) {
        float4 v = *(const float4*)(x + (size_t)t * STRIDE_T_C + idx);
        mem.x = (mem.x - sp.x * 0.5f) * 0.25f + v.x;  sp.x = quant01(mem.x);
        mem.y = (mem.y - sp.y * 0.5f) * 0.25f + v.y;  sp.y = quant01(mem.y);
        mem.z = (mem.z - sp.z * 0.5f) * 0.25f + v.z;  sp.z = quant01(mem.z);
        mem.w = (mem.w - sp.w * 0.5f) * 0.25f + v.w;  sp.w = quant01(mem.w);
        *(uchar4*)(g_s1 + (size_t)t * STRIDE_T_C + idx) =
            make_uchar4((unsigned char)sp.x, (unsigned char)sp.y,
                        (unsigned char)sp.z, (unsigned char)sp.w);
    }
}

// ---------------- fp16 mma.sync spike GEMM (R12) -----------------------------
// TWO=true : y1(fp32) = (W1hi + W1lo*2^-11) * s1 (+bias); single-buffer BK=32.
// TWO=false: zv(fp16) = W2hi * s3; double-buffered smem (1 barrier/chunk).

#define LDA_PAD 40   // 32 + 8 fp16 pad -> conflict-free ldmatrix
#define LDB_PAD 136  // 128 + 8

__device__ __forceinline__ void ldmx4(uint32_t& r0, uint32_t& r1, uint32_t& r2, uint32_t& r3,
                                      const __half* p)
{
    uint32_t a = (uint32_t)__cvta_generic_to_shared(p);
    asm volatile("ldmatrix.sync.aligned.m8n8.x4.shared.b16 {%0,%1,%2,%3}, [%4];"
                 : "=r"(r0), "=r"(r1), "=r"(r2), "=r"(r3) : "r"(a));
}

__device__ __forceinline__ void ldmx2t(uint32_t& r0, uint32_t& r1, const __half* p)
{
    uint32_t a = (uint32_t)__cvta_generic_to_shared(p);
    asm volatile("ldmatrix.sync.aligned.m8n8.x2.trans.shared.b16 {%0,%1}, [%2];"
                 : "=r"(r0), "=r"(r1) : "r"(a));
}

__device__ __forceinline__ void mma16816h(float* c, uint32_t a0, uint32_t a1, uint32_t a2,
                                          uint32_t a3, uint32_t b0, uint32_t b1)
{
    asm volatile(
        "mma.sync.aligned.m16n8k16.row.col.f32.f16.f16.f32 "
        "{%0,%1,%2,%3}, {%4,%5,%6,%7}, {%8,%9}, {%0,%1,%2,%3};"
        : "+f"(c[0]), "+f"(c[1]), "+f"(c[2]), "+f"(c[3])
        : "r"(a0), "r"(a1), "r"(a2), "r"(a3), "r"(b0), "r"(b1));
}

__device__ __forceinline__ void cvt_spikes(uint4 rB, uint4* dst)
{
    uint32_t out[8];
    uint32_t ws[4] = {rB.x, rB.y, rB.z, rB.w};
#pragma unroll
    for (int q = 0; q < 4; q++) {
        uint32_t w = ws[q];
        out[q * 2 + 0] = ((w)       & 1u) * 0x3C00u | ((w >> 8)  & 1u) * 0x3C000000u;
        out[q * 2 + 1] = ((w >> 16) & 1u) * 0x3C00u | ((w >> 24) & 1u) * 0x3C000000u;
    }
    dst[0] = make_uint4(out[0], out[1], out[2], out[3]);
    dst[1] = make_uint4(out[4], out[5], out[6], out[7]);
}

template <int M, int K, bool BIAS, bool TWO>
__device__ __forceinline__ void gemm_tc_body(const __half* __restrict__ Ahi,
                                             const __half* __restrict__ Alo,
                                             const unsigned char* __restrict__ Bspk,
                                             void* __restrict__ Cout,
                                             const float* __restrict__ bias)
{
    constexpr int NBUF = TWO ? 1 : 2;
    int img = blockIdx.z;
    const unsigned char* Bp = Bspk + (size_t)img * K * HW;
    int m0 = blockIdx.y * 128;
    int n0 = blockIdx.x * 128;

    __shared__ __align__(16) __half Ahs[NBUF][128 * LDA_PAD];
    __shared__ __align__(16) __half Als[1][TWO ? 128 * LDA_PAD : 8];
    __shared__ __align__(16) __half Bs[NBUF][32 * LDB_PAD];

    int tid  = threadIdx.x;
    int warp = tid >> 5, lane = tid & 31;
    int warp_m = (warp & 1) * 64;
    int warp_n = (warp >> 1) * 32;

    float accA[4][4][4];
    float accB[TWO ? 4 : 1][4][4];
#pragma unroll
    for (int i = 0; i < 4; i++)
#pragma unroll
        for (int j = 0; j < 4; j++)
#pragma unroll
            for (int q = 0; q < 4; q++) accA[i][j][q] = 0.f;
    if (TWO) {
#pragma unroll
        for (int i = 0; i < 4; i++)
#pragma unroll
            for (int j = 0; j < 4; j++)
#pragma unroll
                for (int q = 0; q < 4; q++) accB[i][j][q] = 0.f;
    }

    int arow = tid >> 1;
    int acol = (tid & 1) * 16;
    int brow = tid >> 3;
    int bcol = (tid & 7) * 16;

    const __half* pAh = Ahi + (size_t)(m0 + arow) * K + acol;
    const __half* pAl = TWO ? (Alo + (size_t)(m0 + arow) * K + acol) : nullptr;
    const unsigned char* pB = Bp + (size_t)brow * HW + n0 + bcol;

    uint4 rAh0, rAh1, rAl0 = {}, rAl1 = {}, rB;

    rAh0 = *(const uint4*)(pAh);
    rAh1 = *(const uint4*)(pAh + 8);
    if (TWO) {
        rAl0 = *(const uint4*)(pAl);
        rAl1 = *(const uint4*)(pAl + 8);
    }
    rB   = *(const uint4*)(pB);

    {
        *(uint4*)&Ahs[0][arow * LDA_PAD + acol]     = rAh0;
        *(uint4*)&Ahs[0][arow * LDA_PAD + acol + 8] = rAh1;
        if (TWO) {
            *(uint4*)&Als[0][arow * LDA_PAD + acol]     = rAl0;
            *(uint4*)&Als[0][arow * LDA_PAD + acol + 8] = rAl1;
        }
        cvt_spikes(rB, (uint4*)&Bs[0][brow * LDB_PAD + bcol]);
    }
    __syncthreads();

    int buf = 0;
    for (int kc = 0; kc < K; kc += 32) {
        bool has_next = (kc + 32 < K);
        if (has_next) {
            rAh0 = *(const uint4*)(pAh + (kc + 32));
            rAh1 = *(const uint4*)(pAh + (kc + 32) + 8);
            if (TWO) {
                rAl0 = *(const uint4*)(pAl + (kc + 32));
                rAl1 = *(const uint4*)(pAl + (kc + 32) + 8);
            }
            rB   = *(const uint4*)(pB + (size_t)(kc + 32) * HW);
        }

#pragma unroll
        for (int ks = 0; ks < 2; ks++) {
            int koff = ks * 16;
            uint32_t bf[4][2];
#pragma unroll
            for (int ni = 0; ni < 4; ni++) {
                const __half* p = &Bs[buf][(koff + (lane & 15)) * LDB_PAD + warp_n + ni * 8];
                ldmx2t(bf[ni][0], bf[ni][1], p);
            }
#pragma unroll
            for (int mi = 0; mi < 4; mi++) {
                int row = warp_m + mi * 16 + (lane & 15);
                int col = koff + (lane >> 4) * 8;
                uint32_t a0, a1, a2, a3;
                ldmx4(a0, a1, a2, a3, &Ahs[buf][row * LDA_PAD + col]);
#pragma unroll
                for (int ni = 0; ni < 4; ni++)
                    mma16816h(accA[mi][ni], a0, a1, a2, a3, bf[ni][0], bf[ni][1]);
                if (TWO) {
                    ldmx4(a0, a1, a2, a3, &Als[0][row * LDA_PAD + col]);
#pragma unroll
                    for (int ni = 0; ni < 4; ni++)
                        mma16816h(accB[mi][ni], a0, a1, a2, a3, bf[ni][0], bf[ni][1]);
                }
            }
        }

        if (has_next) {
            if (!TWO) {
                int nb = buf ^ 1;
                *(uint4*)&Ahs[nb][arow * LDA_PAD + acol]     = rAh0;
                *(uint4*)&Ahs[nb][arow * LDA_PAD + acol + 8] = rAh1;
                cvt_spikes(rB, (uint4*)&Bs[nb][brow * LDB_PAD + bcol]);
                __syncthreads();
                buf = nb;
            } else {
                __syncthreads();
                *(uint4*)&Ahs[0][arow * LDA_PAD + acol]     = rAh0;
                *(uint4*)&Ahs[0][arow * LDA_PAD + acol + 8] = rAh1;
                *(uint4*)&Als[0][arow * LDA_PAD + acol]     = rAl0;
                *(uint4*)&Als[0][arow * LDA_PAD + acol + 8] = rAl1;
                cvt_spikes(rB, (uint4*)&Bs[0][brow * LDB_PAD + bcol]);
                __syncthreads();
            }
        }
    }

    // ---- epilogue ----
#pragma unroll
    for (int mi = 0; mi < 4; mi++) {
        int r0 = m0 + warp_m + mi * 16 + (lane >> 2);
        int r1 = r0 + 8;
        float b0 = BIAS ? bias[r0] : 0.f;
        float b1 = BIAS ? bias[r1] : 0.f;
#pragma unroll
        for (int ni = 0; ni < 4; ni++) {
            int c = n0 + warp_n + ni * 8 + (lane & 3) * 2;
            if (TWO) {
                float* Cp = (float*)Cout + (size_t)img * M * HW;
                float o0 = fmaf(accB[mi][ni][0], LO_INV, accA[mi][ni][0]) + b0;
                float o1 = fmaf(accB[mi][ni][1], LO_INV, accA[mi][ni][1]) + b0;
                float o2 = fmaf(accB[mi][ni][2], LO_INV, accA[mi][ni][2]) + b1;
                float o3 = fmaf(accB[mi][ni][3], LO_INV, accA[mi][ni][3]) + b1;
                *(float2*)(Cp + (size_t)r0 * HW + c) = make_float2(o0, o1);
                *(float2*)(Cp + (size_t)r1 * HW + c) = make_float2(o2, o3);
            } else {
                __half* Cp = (__half*)Cout + (size_t)img * M * HW;
                *(__half2*)(Cp + (size_t)r0 * HW + c) =
                    __floats2half2_rn(accA[mi][ni][0] + b0, accA[mi][ni][1] + b0);
                *(__half2*)(Cp + (size_t)r1 * HW + c) =
                    __floats2half2_rn(accA[mi][ni][2] + b1, accA[mi][ni][3] + b1);
            }
        }
    }
}

__global__ void __launch_bounds__(256) gemm1_kernel()
{
    gemm_tc_body<MED, C_, true, true>(g_W1hi, g_W1lo, g_s1, g_y1, g_bias1);
}

__global__ void __launch_bounds__(256) gemm2_kernel()
{
    gemm_tc_body<C_, MED, false, false>(g_W2hi, nullptr, g_s3, g_zv, nullptr);
}

// ---------------- vector-tap 3x3 conv helper (fp16 tile) --------------------
__device__ __forceinline__ void conv_row_h(float conv[4], const __half* rowp,
                                           float wm, float wc, float wp)
{
    __half2 h01 = *(const __half2*)(rowp);
    __half2 h23 = *(const __half2*)(rowp + 2);
    __half2 h45 = *(const __half2*)(rowp + 4);
    float2 f01 = __half22float2(h01);
    float2 f23 = __half22float2(h23);
    float2 f45 = __half22float2(h45);
    conv[0] = fmaf(wm, f01.x, conv[0]); conv[0] = fmaf(wc, f01.y, conv[0]); conv[0] = fmaf(wp, f23.x, conv[0]);
    conv[1] = fmaf(wm, f01.y, conv[1]); conv[1] = fmaf(wc, f23.x, conv[1]); conv[1] = fmaf(wp, f23.y, conv[1]);
    conv[2] = fmaf(wm, f23.x, conv[2]); conv[2] = fmaf(wc, f23.y, conv[2]); conv[2] = fmaf(wp, f45.x, conv[2]);
    conv[3] = fmaf(wm, f23.y, conv[3]); conv[3] = fmaf(wc, f45.x, conv[3]); conv[3] = fmaf(wp, f45.y, conv[3]);
}

// ---------------- fused LIF2 + dw3x3+BN2 + LIF3 (+ y1 prefetch) -------------
__global__ void __launch_bounds__(256) mid_kernel()
{
    int bx = blockIdx.x;
    int b  = bx >> 9;
    int c  = bx & 511;
    size_t chanbase = ((size_t)b * MED + c) * HW;

    __shared__ __align__(16) __half tile[2][PTILE];

    int tid = threadIdx.x;
    {
        uint32_t* tz = (uint32_t*)&tile[0][0];
#pragma unroll
        for (int i = 0; i < 5; i++) {
            int p = tid + i * 256;
            if (p < PTILE) tz[p] = 0u;
        }
    }

    float wreg[9];
#pragma unroll
    for (int j = 0; j < 9; j++) wreg[j] = g_wdw2f[c * 9 + j];
    float cc = g_c2[c];

    int h  = tid >> 3;
    int w0 = (tid & 7) * 4;
    int pc = (h + 1) * PW + (w0 + 1);
    int rowbase = h * PW + w0;

    size_t pix = chanbase + (h << 5) + w0;

    float mem2[4] = {0, 0, 0, 0}, sp2[4] = {0, 0, 0, 0};
    float mem3[4] = {0, 0, 0, 0}, sp3[4] = {0, 0, 0, 0};

    // prefetch t=0 input
    float4 v = *(const float4*)(g_y1 + pix);

    __syncthreads();

#pragma unroll
    for (int t = 0; t < T_; t++) {
        int buf = t & 1;
        size_t base = (size_t)t * STRIDE_T_M + pix;
        float vv[4] = {v.x, v.y, v.z, v.w};
#pragma unroll
        for (int i = 0; i < 4; i++) {
            mem2[i] = (mem2[i] - sp2[i] * 0.5f) * 0.25f + vv[i];
            sp2[i]  = quant01(mem2[i]);
            tile[buf][pc + i] = __float2half_rn(sp2[i]);
        }
        // prefetch next t's input before the barrier (overlaps with conv)
        if (t + 1 < T_)
            v = *(const float4*)(g_y1 + (size_t)(t + 1) * STRIDE_T_M + pix);
        __syncthreads();

        float conv[4] = {0.f, 0.f, 0.f, 0.f};
        conv_row_h(conv, &tile[buf][rowbase],          wreg[0], wreg[1], wreg[2]);
        conv_row_h(conv, &tile[buf][rowbase + PW],     wreg[3], wreg[4], wreg[5]);
        conv_row_h(conv, &tile[buf][rowbase + 2 * PW], wreg[6], wreg[7], wreg[8]);

        unsigned char sb[4];
#pragma unroll
        for (int i = 0; i < 4; i++) {
            float y2v = conv[i] + cc;
            mem3[i] = (mem3[i] - sp3[i] * 0.5f) * 0.25f + y2v;
            sp3[i]  = quant01(mem3[i]);
            sb[i]   = (unsigned char)sp3[i];
        }
        *(uchar4*)(g_s3 + base) = make_uchar4(sb[0], sb[1], sb[2], sb[3]);
    }
}

// ---------------- final dw3x3 (fp16 zv tile, fp32 conv) ---------------------
__global__ void __launch_bounds__(256) dw3_kernel(float* __restrict__ out)
{
    int plane = blockIdx.x;
    int o = plane & 255;
    size_t base = (size_t)plane * HW;

    __shared__ __align__(16) __half tile[PTILE];

    int tid = threadIdx.x;
    {
        uint32_t* tz = (uint32_t*)&tile[0];
#pragma unroll
        for (int i = 0; i < 3; i++) {
            int p = tid + i * 256;
            if (p < PTILE / 2) tz[p] = 0u;
        }
    }

    float wreg[9];
#pragma unroll
    for (int j = 0; j < 9; j++) wreg[j] = g_wr2f[o * 9 + j];
    float bt = g_Bt[o];

    int h  = tid >> 3;
    int w0 = (tid & 7) * 4;
    int pc = (h + 1) * PW + (w0 + 1);
    int rowbase = h * PW + w0;

    __syncthreads();
    {
        uint2 v = *(const uint2*)(g_zv + base + (h << 5) + w0);
        __half2 p0 = *(__half2*)&v.x;
        __half2 p1 = *(__half2*)&v.y;
        tile[pc + 0] = __low2half(p0);
        tile[pc + 1] = __high2half(p0);
        tile[pc + 2] = __low2half(p1);
        tile[pc + 3] = __high2half(p1);
    }
    __syncthreads();

    float conv[4] = {0.f, 0.f, 0.f, 0.f};
    conv_row_h(conv, &tile[rowbase],          wreg[0], wreg[1], wreg[2]);
    conv_row_h(conv, &tile[rowbase + PW],     wreg[3], wreg[4], wreg[5]);
    conv_row_h(conv, &tile[rowbase + 2 * PW], wreg[6], wreg[7], wreg[8]);

    float4 r = make_float4(conv[0] + bt, conv[1] + bt, conv[2] + bt, conv[3] + bt);
    *(float4*)(out + base + (h << 5) + w0) = r;
}

// ---------------- launch ---------------------------------------------------
extern "C" void kernel_launch(void* const* d_in, const int* in_sizes, int n_in,
                              void* d_out, int out_size)
{
    const float* x      = (const float*)d_in[0];
    const float* w_pw1  = (const float*)d_in[1];
    const float* g1 = (const float*)d_in[2];
    const float* b1 = (const float*)d_in[3];
    const float* m1 = (const float*)d_in[4];
    const float* v1 = (const float*)d_in[5];
    const float* w_dw2  = (const float*)d_in[6];
    const float* g2 = (const float*)d_in[7];
    const float* b2 = (const float*)d_in[8];
    const float* m2 = (const float*)d_in[9];
    const float* v2 = (const float*)d_in[10];
    const float* gp = (const float*)d_in[11];
    const float* bp = (const float*)d_in[12];
    const float* mp = (const float*)d_in[13];
    const float* vp = (const float*)d_in[14];
    const float* w_rep1 = (const float*)d_in[15];
    const float* w_rep2 = (const float*)d_in[16];
    const float* g3 = (const float*)d_in[17];
    const float* b3 = (const float*)d_in[18];
    const float* m3 = (const float*)d_in[19];
    const float* v3 = (const float*)d_in[20];
    float* out = (float*)d_out;

    prep_all<<<1025, 256>>>(w_pw1, g1, b1, m1, v1, w_dw2, g2, b2, m2, v2,
                            gp, bp, mp, vp, w_rep1, w_rep2, g3, b3, m3, v3);

    lif1_kernel<<<(int)(STRIDE_T_C / 1024), 256>>>(x);

    gemm1_kernel<<<dim3(HW / 128, MED / 128, IMGS), 256>>>();   // (8,4,64)

    mid_kernel<<<B_ * MED, 256>>>();                            // 8192 blocks

    gemm2_kernel<<<dim3(HW / 128, C_ / 128, IMGS), 256>>>();    // (8,2,64)

    dw3_kernel<<<IMGS * C_, 256>>>(out);                        // 16384 blocks
}